// round 17
// baseline (speedup 1.0000x reference)
#include <cuda_runtime.h>
#include <cstdint>

#define S_PER_BLK 4
#define T_STEPS   1024
#define H_DIM     64
#define G_DIM     256   // 4*H
#define D_DIM     4
#define NTHREADS  640   // G0 256 + G1 256 + G2 128
#define G0_SZ     256
#define G1_SZ     256
#define G2_SZ     128
#define RING_D    4
#define RSTR      68    // padded ring row stride (floats)
#define H2S_STR   68    // padded h2 row stride

// named barrier ids (0 reserved for __syncthreads)
#define BAR_READY  1   // 1..4  (p)  G0 arrive(256) / G1 sync(256) -> count 512
#define BAR_FREE   5   // 5..8  (p)  G1 arrive / G0 sync -> 512 (G1 primes 4)
#define BAR_PART2  9   // 9..10 (q)  G2 arrive(128) / G1 sync(256) -> 384
#define BAR_H2RDY  11  // 11..12 (q) G1 arrive(256) / G2 sync(128) -> 384 (G1 primes q=1)
#define BAR_L0INT  13  // G0-internal, 256
#define BAR_L1INT  14  // G1-internal, 256

typedef unsigned long long ull;

__device__ __forceinline__ void bar_sync(int id, int cnt) {
    asm volatile("bar.sync %0, %1;" :: "r"(id), "r"(cnt) : "memory");
}
__device__ __forceinline__ void bar_arrive(int id, int cnt) {
    asm volatile("bar.arrive %0, %1;" :: "r"(id), "r"(cnt) : "memory");
}

// ---- fast activations: single-MUFU tanh.approx ----
__device__ __forceinline__ float ftanh(float x) {
    float r;
    asm("tanh.approx.f32 %0, %1;" : "=f"(r) : "f"(x));
    return r;
}
__device__ __forceinline__ float fsig(float x) {
    float r;
    asm("tanh.approx.f32 %0, %1;" : "=f"(r) : "f"(0.5f * x));
    return __fmaf_rn(0.5f, r, 0.5f);
}

// ---- packed f32x2 fma (sm_100+) ----
__device__ __forceinline__ void fma2(ull& d, ull a, ull b, ull c) {
    asm("fma.rn.f32x2 %0, %1, %2, %3;" : "=l"(d) : "l"(a), "l"(b), "l"(c));
}
__device__ __forceinline__ float fold2(ull a) {
    float lo, hi;
    asm("mov.b64 {%0,%1}, %2;" : "=f"(lo), "=f"(hi) : "l"(a));
    return lo + hi;
}
__device__ __forceinline__ ull packf2(float lo, float hi) {
    ull r; asm("mov.b64 %0, {%1,%2};" : "=l"(r) : "f"(lo), "f"(hi)); return r;
}
__device__ __forceinline__ ull f4lo(const float4& v) {
    ull r; asm("mov.b64 %0, {%1,%2};" : "=l"(r) : "f"(v.x), "f"(v.y)); return r;
}
__device__ __forceinline__ ull f4hi(const float4& v) {
    ull r; asm("mov.b64 %0, {%1,%2};" : "=l"(r) : "f"(v.z), "f"(v.w)); return r;
}

// ---- bf16 pack + m16n8k16 bf16 MMA (sm_80+) ----
__device__ __forceinline__ uint32_t pack_bf16x2(float lo, float hi) {
    uint32_t r;
    asm("cvt.rn.bf16x2.f32 %0, %1, %2;" : "=r"(r) : "f"(hi), "f"(lo));
    return r;
}
__device__ __forceinline__ void mma_bf16(float& d0, float& d1, float& d2, float& d3,
                                         uint32_t a0, uint32_t a1, uint32_t a2, uint32_t a3,
                                         uint32_t b0, uint32_t b1) {
    asm volatile("mma.sync.aligned.m16n8k16.row.col.f32.bf16.bf16.f32 "
                 "{%0,%1,%2,%3}, {%4,%5,%6,%7}, {%8,%9}, {%0,%1,%2,%3};"
                 : "+f"(d0), "+f"(d1), "+f"(d2), "+f"(d3)
                 : "r"(a0), "r"(a1), "r"(a2), "r"(a3), "r"(b0), "r"(b1));
}

// smem layout (floats):
//   xs   : S*T*D          = 16384
//   ring : RING_D*S*RSTR  = 1088   (h1 ring, G0 -> G1; classifier scratch after loop)
//   h2s  : 2*S*H2S_STR    = 544    (h2 double buffer, G1 -> G2)
//   ga0  : S*G            = 1024   (layer-0 gate exchange within G0)
//   ga1  : S*G            = 1024   (layer-1 gate exchange within G1)
//   pp   : 2*256*4        = 2048   (part2, row-indexed [q][row][sample], G2 -> G1)
//   b1s  : 256                     (b1 staged for G2 bias init)
// total 22368 floats = 89472 bytes

__global__ __launch_bounds__(NTHREADS, 1)
void lstm_fused_kernel(const float* __restrict__ x,
                       const float* __restrict__ W_ih0,
                       const float* __restrict__ W_hh0,
                       const float* __restrict__ b0,
                       const float* __restrict__ W_ih1,
                       const float* __restrict__ W_hh1,
                       const float* __restrict__ b1,
                       const float* __restrict__ W_fc1,
                       const float* __restrict__ b_fc1,
                       const float* __restrict__ W_fc2,
                       const float* __restrict__ b_fc2,
                       float* __restrict__ out)
{
    extern __shared__ float sm[];
    float* xs   = sm;                                   // [S][T][D]
    float* ring = sm + S_PER_BLK * T_STEPS * D_DIM;     // [RING_D][S][RSTR]
    float* h2s  = ring + RING_D * S_PER_BLK * RSTR;     // [2][S][H2S_STR]
    float* ga0  = h2s + 2 * S_PER_BLK * H2S_STR;        // [S][G]
    float* ga1  = ga0 + S_PER_BLK * G_DIM;              // [S][G]
    float* pp   = ga1 + S_PER_BLK * G_DIM;              // [2][256][4]
    float* b1s  = pp + 2 * 256 * 4;                     // [256]

    const int tid = threadIdx.x;
    const int bb  = blockIdx.x * S_PER_BLK;

    // ---- common staging ----
    {
        const float4* gx = (const float4*)(x + (size_t)bb * T_STEPS * D_DIM);
        float4*       sx = (float4*)xs;
        #pragma unroll 4
        for (int i = tid; i < S_PER_BLK * T_STEPS; i += NTHREADS) sx[i] = gx[i];
    }
    for (int i = tid; i < RING_D * S_PER_BLK * RSTR; i += NTHREADS) ring[i] = 0.f;
    for (int i = tid; i < 2 * S_PER_BLK * H2S_STR; i += NTHREADS) h2s[i] = 0.f;
    for (int i = tid; i < G_DIM; i += NTHREADS) b1s[i] = b1[i];

    __syncthreads();

    if (tid < G0_SZ) {
        // ===== G0: layer 0, scalar, ONE row per thread (R8 structure + R9 preload) =====
        const int g  = tid;
        const int us = g >> 6, uh = g & 63;
        const bool is_tanh = (g >= 2 * H_DIM) && (g < 3 * H_DIM);

        float4 w0[16];
        {
            const float4* p0 = (const float4*)(W_hh0 + g * H_DIM);
            #pragma unroll
            for (int i = 0; i < 16; i++) w0[i] = p0[i];
        }
        float wi0[D_DIM];
        #pragma unroll
        for (int d = 0; d < D_DIM; d++) wi0[d] = W_ih0[g * D_DIM + d];
        const float bias0 = b0[g];
        float c1r = 0.f;

        for (int t = 0; t < T_STEPS; t++) {
            const int p = t & 3;
            bar_sync(BAR_FREE + p, G0_SZ + G1_SZ);       // primed by G1

            const float* h1base = ring + ((t - 1) & 3) * S_PER_BLK * RSTR;

            ull acc[S_PER_BLK];
            #pragma unroll
            for (int s = 0; s < S_PER_BLK; s++) {
                const float4 xv = ((const float4*)xs)[s * T_STEPS + t];
                float iv = bias0;
                iv = __fmaf_rn(xv.x, wi0[0], iv);
                iv = __fmaf_rn(xv.y, wi0[1], iv);
                iv = __fmaf_rn(xv.z, wi0[2], iv);
                iv = __fmaf_rn(xv.w, wi0[3], iv);
                acc[s] = packf2(iv, 0.f);
            }
            #pragma unroll
            for (int k = 0; k < 16; k++) {
                #pragma unroll
                for (int s = 0; s < S_PER_BLK; s++) {
                    const float4 hv = ((const float4*)(h1base + s * RSTR))[k];
                    fma2(acc[s], f4lo(w0[k]), f4lo(hv), acc[s]);
                    fma2(acc[s], f4hi(w0[k]), f4hi(hv), acc[s]);
                }
            }
            #pragma unroll
            for (int s = 0; s < S_PER_BLK; s++) {
                const float pre = fold2(acc[s]);
                ga0[s * G_DIM + g] = is_tanh ? ftanh(pre) : fsig(pre);
            }
            bar_sync(BAR_L0INT, G0_SZ);                  // ga0 ready

            {
                const float iv = ga0[us * G_DIM + uh];
                const float fv = ga0[us * G_DIM + uh + H_DIM];
                const float gv = ga0[us * G_DIM + uh + 2 * H_DIM];
                const float ov = ga0[us * G_DIM + uh + 3 * H_DIM];
                c1r = __fmaf_rn(fv, c1r, iv * gv);
                ring[p * S_PER_BLK * RSTR + us * RSTR + uh] = ov * ftanh(c1r);
            }
            bar_arrive(BAR_READY + p, G0_SZ + G1_SZ);    // publish h1(t)
        }
    } else if (tid < G0_SZ + G1_SZ) {
        // ===== G1: layer-1 critical path, scalar, ONE row of W_ih1 per thread =====
        const int g  = tid - G0_SZ;
        const int us = g >> 6, uh = g & 63;
        const bool is_tanh = (g >= 2 * H_DIM) && (g < 3 * H_DIM);

        float4 w1[16];
        {
            const float4* p1 = (const float4*)(W_ih1 + g * H_DIM);
            #pragma unroll
            for (int i = 0; i < 16; i++) w1[i] = p1[i];
        }
        float c2r = 0.f;

        // prime: RING_D free ring slots; h2(-1) "ready" in h2s[1]
        #pragma unroll
        for (int p = 0; p < RING_D; p++) bar_arrive(BAR_FREE + p, G0_SZ + G1_SZ);
        bar_arrive(BAR_H2RDY + 1, G1_SZ + G2_SZ);

        for (int t = 0; t < T_STEPS; t++) {
            const int p = t & 3;
            const int q = t & 1;

            bar_sync(BAR_READY + p, G0_SZ + G1_SZ);      // h1(t) ready

            const float* h1c = ring + p * S_PER_BLK * RSTR;
            ull acc[S_PER_BLK];
            #pragma unroll
            for (int s = 0; s < S_PER_BLK; s++) acc[s] = 0ULL;
            #pragma unroll
            for (int k = 0; k < 16; k++) {
                #pragma unroll
                for (int s = 0; s < S_PER_BLK; s++) {
                    const float4 hv = ((const float4*)(h1c + s * RSTR))[k];
                    fma2(acc[s], f4lo(w1[k]), f4lo(hv), acc[s]);
                    fma2(acc[s], f4hi(w1[k]), f4hi(hv), acc[s]);
                }
            }
            bar_arrive(BAR_FREE + p, G0_SZ + G1_SZ);     // done reading ring[p]

            bar_sync(BAR_PART2 + q, G1_SZ + G2_SZ);      // part2(t) ready from G2
            const float4 ppv = ((const float4*)pp)[q * 256 + g];
            {
                float pre0 = fold2(acc[0]) + ppv.x;
                float pre1 = fold2(acc[1]) + ppv.y;
                float pre2 = fold2(acc[2]) + ppv.z;
                float pre3 = fold2(acc[3]) + ppv.w;
                ga1[0 * G_DIM + g] = is_tanh ? ftanh(pre0) : fsig(pre0);
                ga1[1 * G_DIM + g] = is_tanh ? ftanh(pre1) : fsig(pre1);
                ga1[2 * G_DIM + g] = is_tanh ? ftanh(pre2) : fsig(pre2);
                ga1[3 * G_DIM + g] = is_tanh ? ftanh(pre3) : fsig(pre3);
            }
            bar_sync(BAR_L1INT, G1_SZ);                  // ga1 ready

            {
                const float iv = ga1[us * G_DIM + uh];
                const float fv = ga1[us * G_DIM + uh + H_DIM];
                const float gv = ga1[us * G_DIM + uh + 2 * H_DIM];
                const float ov = ga1[us * G_DIM + uh + 3 * H_DIM];
                c2r = __fmaf_rn(fv, c2r, iv * gv);
                h2s[q * S_PER_BLK * H2S_STR + us * H2S_STR + uh] = ov * ftanh(c2r);
            }
            bar_arrive(BAR_H2RDY + q, G1_SZ + G2_SZ);    // publish h2(t)
        }
    } else {
        // ===== G2: shadow part2 = b1 + h2(t-1)*W_hh1^T via bf16 m16n8k16 MMA =====
        // warp w covers original rows [64w, 64w+64): 4 m16 tiles; K=64 as 4 k16 chunks.
        const int t2    = tid - G0_SZ - G1_SZ;
        const int warp  = t2 >> 5;
        const int lane  = t2 & 31;
        const int gid   = lane >> 2;            // groupID (row within tile)
        const int tg    = lane & 3;             // threadID in group
        const int s     = gid & 3;              // B column = sample (cols 4-7 dup)
        const int rbase = 64 * warp + gid;

        // A fragments: W_hh1 rows in bf16x2 (64 regs)
        uint32_t A[4][4][4];
        #pragma unroll
        for (int i = 0; i < 4; i++) {
            const float* wr1 = W_hh1 + (rbase + 16 * i) * H_DIM;
            const float* wr2 = wr1 + 8 * H_DIM;
            #pragma unroll
            for (int c = 0; c < 4; c++) {
                const int k = 16 * c + 2 * tg;
                A[i][c][0] = pack_bf16x2(wr1[k],     wr1[k + 1]);
                A[i][c][1] = pack_bf16x2(wr2[k],     wr2[k + 1]);
                A[i][c][2] = pack_bf16x2(wr1[k + 8], wr1[k + 9]);
                A[i][c][3] = pack_bf16x2(wr2[k + 8], wr2[k + 9]);
            }
        }

        for (int t = 0; t < T_STEPS; t++) {
            const int q  = t & 1;
            const int qr = (t - 1) & 1;          // h2(t-1): t=0 -> h2s[1] (zeros)

            bar_sync(BAR_H2RDY + qr, G1_SZ + G2_SZ);     // h2(t-1) ready

            const float* h2p = h2s + qr * S_PER_BLK * H2S_STR + s * H2S_STR;
            float d[4][4];
            #pragma unroll
            for (int i = 0; i < 4; i++) {
                const float bl = b1s[rbase + 16 * i];
                const float bh = b1s[rbase + 16 * i + 8];
                d[i][0] = bl; d[i][1] = bl;
                d[i][2] = bh; d[i][3] = bh;
            }
            #pragma unroll
            for (int c = 0; c < 4; c++) {
                const int k = 16 * c + 2 * tg;
                const uint32_t b0v = pack_bf16x2(h2p[k],     h2p[k + 1]);
                const uint32_t b1v = pack_bf16x2(h2p[k + 8], h2p[k + 9]);
                #pragma unroll
                for (int i = 0; i < 4; i++) {
                    mma_bf16(d[i][0], d[i][1], d[i][2], d[i][3],
                             A[i][c][0], A[i][c][1], A[i][c][2], A[i][c][3],
                             b0v, b1v);
                }
            }
            // store valid columns (samples 0-3 live in lanes with tg<2)
            if (tg < 2) {
                float* ppq = pp + q * 256 * 4;
                const int sb = 2 * tg;
                #pragma unroll
                for (int i = 0; i < 4; i++) {
                    const int R1 = rbase + 16 * i;
                    *(float2*)(ppq + R1 * 4 + sb)       = make_float2(d[i][0], d[i][1]);
                    *(float2*)(ppq + (R1 + 8) * 4 + sb) = make_float2(d[i][2], d[i][3]);
                }
            }
            bar_arrive(BAR_PART2 + q, G1_SZ + G2_SZ);    // part2(t) published
        }
    }

    __syncthreads();

    // ---------- classifier (ring reused as scratch); h2 final in h2s[1] ----------
    const float* h2f = h2s + ((T_STEPS - 1) & 1) * S_PER_BLK * H2S_STR;
    if (tid < S_PER_BLK * 32) {
        int s = tid >> 5, jj = tid & 31;
        float a = b_fc1[jj];
        #pragma unroll
        for (int k = 0; k < H_DIM; k++)
            a = __fmaf_rn(h2f[s * H2S_STR + k], W_fc1[jj * H_DIM + k], a);
        ring[s * 32 + jj] = fmaxf(a, 0.f);
    }
    __syncthreads();
    if (tid < S_PER_BLK) {
        float a = b_fc2[0];
        #pragma unroll
        for (int jj = 0; jj < 32; jj++)
            a = __fmaf_rn(ring[tid * 32 + jj], W_fc2[jj], a);
        out[bb + tid] = fsig(a);
    }
}

extern "C" void kernel_launch(void* const* d_in, const int* in_sizes, int n_in,
                              void* d_out, int out_size)
{
    const float* x     = (const float*)d_in[0];
    const float* W_ih0 = (const float*)d_in[1];
    const float* W_hh0 = (const float*)d_in[2];
    const float* b0    = (const float*)d_in[3];
    const float* W_ih1 = (const float*)d_in[4];
    const float* W_hh1 = (const float*)d_in[5];
    const float* b1    = (const float*)d_in[6];
    const float* W_fc1 = (const float*)d_in[7];
    const float* b_fc1 = (const float*)d_in[8];
    const float* W_fc2 = (const float*)d_in[9];
    const float* b_fc2 = (const float*)d_in[10];
    float* out = (float*)d_out;

    const size_t smem_bytes =
        (size_t)(S_PER_BLK * T_STEPS * D_DIM          // xs
                 + RING_D * S_PER_BLK * RSTR          // ring
                 + 2 * S_PER_BLK * H2S_STR            // h2s
                 + 2 * S_PER_BLK * G_DIM              // ga0, ga1
                 + 2 * 256 * 4                        // pp
                 + G_DIM)                             // b1s
        * sizeof(float);

    cudaFuncSetAttribute(lstm_fused_kernel,
                         cudaFuncAttributeMaxDynamicSharedMemorySize,
                         (int)smem_bytes);

    const int nblocks = 512 / S_PER_BLK;   // 128
    lstm_fused_kernel<<<nblocks, NTHREADS, smem_bytes>>>(
        x, W_ih0, W_hh0, b0, W_ih1, W_hh1, b1,
        W_fc1, b_fc1, W_fc2, b_fc2, out);
}